// round 8
// baseline (speedup 1.0000x reference)
#include <cuda_runtime.h>
#include <cstdint>

// Problem constants
#define BB   2
#define SSL  2048
#define DD   1024
#define HH   16
#define DHH  64
#define MMR  (BB*SSL)   // 4096

// Scratch (__device__ globals; allocation-free rule). All values tf32-rounded.
// Fragment-packed layouts:
//   A-frag pack (16-row groups): word = ((mg*NKD+kd)*32 + (r&7)*4 + (d&3))*4
//                                       + ((r>>3)&1) + 2*((d>>2)&1)
//   B-frag pack (8-col groups):  word = ((ng*NKD+kd)*64) + ((n&7)*4+(d&3))*2
//                                       + ((d>>2)&1)
__device__ float g_q[(size_t)BB*HH*SSL*DHH];   // per (b,h): A-frag pack, q*0.125*log2e
__device__ float g_k[(size_t)BB*HH*SSL*DHH];   // per (b,h): B-frag pack [S][64]
__device__ float g_v[(size_t)BB*HH*SSL*DHH];   // per (b,h): B-frag pack (j<->e swapped)
__device__ float g_ctxp[(size_t)MMR*DD];       // ctx, A-frag pack [4096][1024]
__device__ float g_xp[(size_t)MMR*DD];         // x,   A-frag pack [4096][1024]
__device__ float g_wp[(size_t)3*HH*DD*DHH];    // W{q,k,v}, B-frag pack per head
__device__ float g_wop[(size_t)DD*DD];         // Wo, B-frag pack [1024 n][1024 k]

// ---------------------------------------------------------------------------
// Helpers
// ---------------------------------------------------------------------------
__device__ __forceinline__ uint32_t f2t(float f) {
    uint32_t u;
    asm("cvt.rna.tf32.f32 %0, %1;" : "=r"(u) : "f"(f));
    return u;
}

__device__ __forceinline__ float ex2(float x) {
    float r;
    asm("ex2.approx.f32 %0, %1;" : "=f"(r) : "f"(x));
    return r;
}

__device__ __forceinline__ void mma_tf32(float* c,
                                         uint32_t a0, uint32_t a1, uint32_t a2, uint32_t a3,
                                         uint32_t b0, uint32_t b1) {
    asm volatile(
        "mma.sync.aligned.m16n8k8.row.col.f32.tf32.tf32.f32 "
        "{%0,%1,%2,%3}, {%4,%5,%6,%7}, {%8,%9}, {%0,%1,%2,%3};"
        : "+f"(c[0]), "+f"(c[1]), "+f"(c[2]), "+f"(c[3])
        : "r"(a0), "r"(a1), "r"(a2), "r"(a3), "r"(b0), "r"(b1));
}

__device__ __forceinline__ uint32_t smaddr(const void* p) {
    return (uint32_t)__cvta_generic_to_shared(p);
}
#define CPA16(dst, src) \
    asm volatile("cp.async.cg.shared.global [%0], [%1], 16;" :: "r"(dst), "l"(src))
#define CPA_COMMIT() asm volatile("cp.async.commit_group;")
#define CPA_WAIT(N)  asm volatile("cp.async.wait_group %0;" :: "n"(N))

// Fragment-packed address maps for attn tensors (word index in one (b,h) plane)
__device__ __forceinline__ int qaddr(int r, int d) {
    return ((((r >> 4) * 8 + (d >> 3)) * 32 + (r & 7) * 4 + (d & 3)) << 2)
           | ((r >> 3) & 1) | (((d >> 2) & 1) << 1);
}
__device__ __forceinline__ int kaddr(int j, int d) {
    return ((((j >> 3) * 8 + (d >> 3)) * 32 + (j & 7) * 4 + (d & 3)) << 1)
           | ((d >> 2) & 1);
}
__device__ __forceinline__ int vaddr(int j, int e) {
    return ((((j >> 3) * 8 + (e >> 3)) * 32 + (e & 7) * 4 + (j & 3)) << 1)
           | ((j >> 2) & 1);
}

// ---------------------------------------------------------------------------
// Kernel 0: pack + tf32-round x / Wq / Wk / Wv / Wo into fragment layouts.
// ---------------------------------------------------------------------------
#define XN4  ((size_t)MMR*DD/4)          // 1048576
#define WN4  ((size_t)HH*DD*DHH/4)       // 262144
#define PREP_TOTAL4 (XN4 + 4*WN4)        // 2097152

__global__ __launch_bounds__(256) void prep_pack(
    const float* __restrict__ x,  const float* __restrict__ Wq,
    const float* __restrict__ Wk, const float* __restrict__ Wv,
    const float* __restrict__ Wo)
{
    size_t i = (size_t)blockIdx.x * 256 + threadIdx.x;
    if (i >= PREP_TOTAL4) return;
    if (i < XN4) {
        int r = (int)(i >> 8), d0 = ((int)i & 255) * 4;
        float4 v = ((const float4*)x)[i];
        int mg = r >> 4, kd = d0 >> 3;
        int r8 = (r >> 3) & 1, d4 = (d0 >> 2) & 1;
        size_t w0 = ((((size_t)mg * 128 + kd) * 32 + (r & 7) * 4) << 2) + r8 + 2 * d4;
        g_xp[w0 +  0] = __uint_as_float(f2t(v.x));
        g_xp[w0 +  4] = __uint_as_float(f2t(v.y));
        g_xp[w0 +  8] = __uint_as_float(f2t(v.z));
        g_xp[w0 + 12] = __uint_as_float(f2t(v.w));
    } else if (i < XN4 + 3 * WN4) {
        size_t j = i - XN4;
        int z = (int)(j / WN4);
        int jr = (int)(j - (size_t)z * WN4);
        const float* W = (z == 0) ? Wq : (z == 1) ? Wk : Wv;
        float4 v = ((const float4*)W)[jr];
        int h = jr >> 14, d = (jr >> 4) & 1023, e0 = (jr & 15) * 4;
        int kd = d >> 3, t = d & 3, d4 = (d >> 2) & 1;
        size_t base = ((size_t)(z * 16 + h) * 8 + (e0 >> 3)) * 128 + kd;
        size_t w0 = base * 64 + (size_t)((e0 & 7) * 4 + t) * 2 + d4;
        g_wp[w0 +  0] = __uint_as_float(f2t(v.x));
        g_wp[w0 +  8] = __uint_as_float(f2t(v.y));
        g_wp[w0 + 16] = __uint_as_float(f2t(v.z));
        g_wp[w0 + 24] = __uint_as_float(f2t(v.w));
    } else {
        size_t j = i - XN4 - 3 * WN4;
        float4 v = ((const float4*)Wo)[j];
        int d = (int)(j >> 8), n0 = ((int)j & 255) * 4;
        int kd = d >> 3, t = d & 3, d4 = (d >> 2) & 1;
        size_t w0 = (((size_t)(n0 >> 3) * 128 + kd) * 64)
                  + (size_t)((n0 & 7) * 4 + t) * 2 + d4;
        g_wop[w0 +  0] = __uint_as_float(f2t(v.x));
        g_wop[w0 +  8] = __uint_as_float(f2t(v.y));
        g_wop[w0 + 16] = __uint_as_float(f2t(v.z));
        g_wop[w0 + 24] = __uint_as_float(f2t(v.w));
    }
}

// ---------------------------------------------------------------------------
// GEMM core: block 128x128, BK=32, 8 warps (2m x 4n), warp 64x32.
// 3-stage cp.async ring, ONE __syncthreads per iter, wait_group(1).
// smem: As[3][4096] + Bs[3][4096] words = 96KB.
// ---------------------------------------------------------------------------
#define TILE_W 4096
#define GEMM_SMEM_BYTES (6 * TILE_W * 4)

// ---------------------------------------------------------------------------
// Kernel 1: fused QKV projection. grid=(8,32,3). Epilogue writes packed q/k/v.
// ---------------------------------------------------------------------------
__global__ __launch_bounds__(256, 2) void qkv_kernel(
    const float* __restrict__ bq, const float* __restrict__ bk, const float* __restrict__ bv)
{
    extern __shared__ uint32_t sm[];
    const uint32_t smA = smaddr(sm);                 // As: 3 * 4096 words
    const uint32_t smB = smA + 3 * TILE_W * 4;       // Bs: 3 * 4096 words

    const int z = blockIdx.z;
    const float* __restrict__ bias = (z == 0) ? bq : (z == 1) ? bk : bv;
    float* out = (z == 0) ? g_q : (z == 1) ? g_k : g_v;
    // q carries 1/sqrt(DH) * log2(e) so attn softmax can use raw ex2
    const float scale = (z == 0) ? 0.125f * 1.4426950408889634f : 1.0f;

    const int n0 = blockIdx.x * 128;
    const int m0 = blockIdx.y * 128;
    const int hA = n0 >> 6;
    const int mg0 = m0 >> 4;

    const int tid  = threadIdx.x;
    const int lane = tid & 31;
    const int warp = tid >> 5;
    const int g = lane >> 2, t = lane & 3;

    float acc[4][4][4];
    #pragma unroll
    for (int i = 0; i < 4; i++)
        #pragma unroll
        for (int j = 0; j < 4; j++)
            #pragma unroll
            for (int q = 0; q < 4; q++) acc[i][j][q] = 0.f;

    auto issue_tile = [&](int it2) {
        const int kd0 = it2 * 4;
        const int buf = it2 % 3;
        #pragma unroll
        for (int u = 0; u < 4; u++) {          // A tile: 4096 words
            int w = (u * 256 + tid) * 4;
            int mgl = w >> 9, rem = w & 511;
            const float* src = g_xp + ((size_t)(mg0 + mgl) * 128 + kd0) * 128 + rem;
            CPA16(smA + (uint32_t)(buf * TILE_W + w) * 4, src);
        }
        #pragma unroll
        for (int u = 0; u < 4; u++) {          // B tile: 4096 words
            int w = (u * 256 + tid) * 4;
            int ngl = w >> 8, rem = w & 255;
            int head = hA + (ngl >> 3);
            const float* src = g_wp + (size_t)(z * 16 + head) * 65536
                             + ((size_t)(ngl & 7) * 128 + kd0) * 64 + rem;
            CPA16(smB + (uint32_t)(buf * TILE_W + w) * 4, src);
        }
        CPA_COMMIT();
    };

    issue_tile(0);
    issue_tile(1);

    for (int it = 0; it < 32; it++) {
        if (it == 31) { CPA_WAIT(0); } else { CPA_WAIT(1); }
        __syncthreads();                       // publishes tile(it); frees buf((it-1)%3)
        if (it + 2 < 32) issue_tile(it + 2);

        const uint32_t* As_ = sm + (it % 3) * TILE_W;
        const uint32_t* Bs_ = sm + 3 * TILE_W + (it % 3) * TILE_W;
        #pragma unroll
        for (int ks = 0; ks < 4; ks++) {
            uint4 av[4];
            #pragma unroll
            for (int mt = 0; mt < 4; mt++)
                av[mt] = *(const uint4*)&As_[(((warp >> 2) * 4 + mt) * 4 + ks) * 128 + lane * 4];
            #pragma unroll
            for (int nt = 0; nt < 4; nt++) {
                uint2 bv2 = *(const uint2*)&Bs_[(((warp & 3) * 4 + nt) * 4 + ks) * 64 + lane * 2];
                #pragma unroll
                for (int mt = 0; mt < 4; mt++)
                    mma_tf32(acc[mt][nt], av[mt].x, av[mt].y, av[mt].z, av[mt].w,
                             bv2.x, bv2.y);
            }
        }
    }

    // Epilogue: bias + scale + tf32-round, scatter into fragment-packed q/k/v
    const int wm0 = (warp >> 2) * 64;
    const int wn0 = (warp & 3) * 32;
    #pragma unroll
    for (int mt = 0; mt < 4; mt++) {
        #pragma unroll
        for (int nt = 0; nt < 4; nt++) {
            int cb = n0 + wn0 + nt * 8 + 2 * t;
            float bi0 = bias[cb], bi1 = bias[cb + 1];
            int h = cb >> 6, e0 = cb & 63;
            #pragma unroll
            for (int half = 0; half < 2; half++) {
                int m = m0 + wm0 + mt * 16 + g + half * 8;
                int b = m >> 11, s = m & (SSL - 1);
                float* plane = out + (size_t)(b * HH + h) * (SSL * DHH);
                float v0 = (acc[mt][nt][half * 2 + 0] + bi0) * scale;
                float v1 = (acc[mt][nt][half * 2 + 1] + bi1) * scale;
                if (z == 0) {
                    plane[qaddr(s, e0)]     = __uint_as_float(f2t(v0));
                    plane[qaddr(s, e0 + 1)] = __uint_as_float(f2t(v1));
                } else if (z == 1) {
                    plane[kaddr(s, e0)]     = __uint_as_float(f2t(v0));
                    plane[kaddr(s, e0 + 1)] = __uint_as_float(f2t(v1));
                } else {
                    plane[vaddr(s, e0)]     = __uint_as_float(f2t(v0));
                    plane[vaddr(s, e0 + 1)] = __uint_as_float(f2t(v1));
                }
            }
        }
    }
}

// ---------------------------------------------------------------------------
// Kernel 2: flash attention (R7 core; softmax in base-2 via ex2).
// smem (words): Qs 8192 | Ks 4096 | Vs 4096 | Ps 8704 = 25088 -> 100352 B
// grid = (16, 32), 256 threads, 2 CTAs/SM.
// ---------------------------------------------------------------------------
#define QS_OFF 0
#define KS_OFF 8192
#define VS_OFF 12288
#define PS_OFF 16384
#define ATTN_SMEM_BYTES (25088 * 4)

__global__ __launch_bounds__(256, 2) void attn_kernel()
{
    extern __shared__ uint32_t sm[];

    const int tid  = threadIdx.x;
    const int lane = tid & 31;
    const int warp = tid >> 5;
    const int g = lane >> 2, t = lane & 3;
    const int wr0 = warp * 16;

    const int bh = blockIdx.y;
    const float* __restrict__ Qg = g_q + (size_t)bh * (SSL * DHH) + (size_t)blockIdx.x * 8192;
    const float* __restrict__ Kg = g_k + (size_t)bh * (SSL * DHH);
    const float* __restrict__ Vg = g_v + (size_t)bh * (SSL * DHH);

    const uint32_t smb = smaddr(sm);

    #pragma unroll
    for (int u = 0; u < 8; u++) {
        int c = u * 256 + tid;
        CPA16(smb + (uint32_t)(QS_OFF + c * 4) * 4, Qg + c * 4);
    }
    CPA_COMMIT();
    #pragma unroll
    for (int u = 0; u < 4; u++) {
        int c = u * 256 + tid;
        CPA16(smb + (uint32_t)(KS_OFF + c * 4) * 4, Kg + c * 4);
    }
    CPA_COMMIT();

    float oacc[8][4];
    #pragma unroll
    for (int e = 0; e < 8; e++)
        #pragma unroll
        for (int q = 0; q < 4; q++) oacc[e][q] = 0.f;
    float mrun0 = -1e30f, mrun1 = -1e30f;
    float lrun0 = 0.f, lrun1 = 0.f;

    for (int i = 0; i < 32; i++) {
        CPA_WAIT(0);
        __syncthreads();

        {
            const float* Vt = Vg + (size_t)i * 4096;
            #pragma unroll
            for (int u = 0; u < 4; u++) {
                int c = u * 256 + tid;
                CPA16(smb + (uint32_t)(VS_OFF + c * 4) * 4, Vt + c * 4);
            }
            CPA_COMMIT();
        }

        float sf[8][4];
        #pragma unroll
        for (int jt = 0; jt < 8; jt++)
            #pragma unroll
            for (int q = 0; q < 4; q++) sf[jt][q] = 0.f;

        #pragma unroll
        for (int kd = 0; kd < 8; kd++) {
            uint4 aq = *(const uint4*)&sm[QS_OFF + ((warp * 8 + kd) * 32 + lane) * 4];
            #pragma unroll
            for (int jt = 0; jt < 8; jt++) {
                uint2 kb = *(const uint2*)&sm[KS_OFF + ((jt * 8 + kd) * 32 + lane) * 2];
                mma_tf32(sf[jt], aq.x, aq.y, aq.z, aq.w, kb.x, kb.y);
            }
        }
        __syncthreads();

        if (i + 1 < 32) {
            const float* Kt = Kg + (size_t)(i + 1) * 4096;
            #pragma unroll
            for (int u = 0; u < 4; u++) {
                int c = u * 256 + tid;
                CPA16(smb + (uint32_t)(KS_OFF + c * 4) * 4, Kt + c * 4);
            }
            CPA_COMMIT();
        }

        // Online softmax in base-2 (scores already scaled by log2e in q)
        float mx0 = -1e30f, mx1 = -1e30f;
        #pragma unroll
        for (int jt = 0; jt < 8; jt++) {
            mx0 = fmaxf(mx0, fmaxf(sf[jt][0], sf[jt][1]));
            mx1 = fmaxf(mx1, fmaxf(sf[jt][2], sf[jt][3]));
        }
        mx0 = fmaxf(mx0, __shfl_xor_sync(0xffffffffu, mx0, 1));
        mx0 = fmaxf(mx0, __shfl_xor_sync(0xffffffffu, mx0, 2));
        mx1 = fmaxf(mx1, __shfl_xor_sync(0xffffffffu, mx1, 1));
        mx1 = fmaxf(mx1, __shfl_xor_sync(0xffffffffu, mx1, 2));
        float mn0 = fmaxf(mrun0, mx0), mn1 = fmaxf(mrun1, mx1);
        float corr0 = ex2(mrun0 - mn0), corr1 = ex2(mrun1 - mn1);
        float sum0 = 0.f, sum1 = 0.f;
        #pragma unroll
        for (int jt = 0; jt < 8; jt++) {
            sf[jt][0] = ex2(sf[jt][0] - mn0);
            sf[jt][1] = ex2(sf[jt][1] - mn0);
            sf[jt][2] = ex2(sf[jt][2] - mn1);
            sf[jt][3] = ex2(sf[jt][3] - mn1);
            sum0 += sf[jt][0] + sf[jt][1];
            sum1 += sf[jt][2] + sf[jt][3];
        }
        sum0 += __shfl_xor_sync(0xffffffffu, sum0, 1);
        sum0 += __shfl_xor_sync(0xffffffffu, sum0, 2);
        sum1 += __shfl_xor_sync(0xffffffffu, sum1, 1);
        sum1 += __shfl_xor_sync(0xffffffffu, sum1, 2);
        lrun0 = lrun0 * corr0 + sum0; mrun0 = mn0;
        lrun1 = lrun1 * corr1 + sum1; mrun1 = mn1;
        #pragma unroll
        for (int e = 0; e < 8; e++) {
            oacc[e][0] *= corr0; oacc[e][1] *= corr0;
            oacc[e][2] *= corr1; oacc[e][3] *= corr1;
        }

        if (i < 31) { CPA_WAIT(1); } else { CPA_WAIT(0); }
        __syncthreads();

        const int pr0 = wr0 + g;
        #pragma unroll
        for (int jt = 0; jt < 8; jt++) {
            uint2 p01 = make_uint2(f2t(sf[jt][0]), f2t(sf[jt][1]));
            uint2 p23 = make_uint2(f2t(sf[jt][2]), f2t(sf[jt][3]));
            *(uint2*)&sm[PS_OFF + pr0 * 68 + jt * 8 + 2 * t] = p01;
            *(uint2*)&sm[PS_OFF + (pr0 + 8) * 68 + jt * 8 + 2 * t] = p23;
        }
        __syncwarp();

        #pragma unroll
        for (int kj = 0; kj < 8; kj++) {
            const int k8 = kj * 8;
            uint32_t a0 = sm[PS_OFF + (wr0 + g) * 68 + k8 + t];
            uint32_t a1 = sm[PS_OFF + (wr0 + g + 8) * 68 + k8 + t];
            uint32_t a2 = sm[PS_OFF + (wr0 + g) * 68 + k8 + t + 4];
            uint32_t a3 = sm[PS_OFF + (wr0 + g + 8) * 68 + k8 + t + 4];
            #pragma unroll
            for (int et = 0; et < 8; et++) {
                uint2 vb = *(const uint2*)&sm[VS_OFF + ((kj * 8 + et) * 32 + lane) * 2];
                mma_tf32(oacc[et], a0, a1, a2, a3, vb.x, vb.y);
            }
        }
    }

    // Epilogue: normalize, tf32-round, write ctx in A-frag packed layout
    const int b = bh >> 4, h = bh & 15;
    const int m0 = blockIdx.x * 128;
    const float inv0 = 1.f / lrun0, inv1 = 1.f / lrun1;
    const int row0 = m0 + wr0 + g;
    const int mrow = (b << 11) + row0;
    const int mg = mrow >> 4;
    #pragma unroll
    for (int et = 0; et < 8; et++) {
        int d = h * DHH + et * 8 + 2 * t;
        int kd = d >> 3, d4 = (d >> 2) & 1;
        size_t w0 = ((((size_t)mg * 128 + kd) * 32 + (mrow & 7) * 4 + (d & 3)) << 2)
                  + 2 * d4;
        g_ctxp[w0 + 0] = __uint_as_float(f2t(oacc[et][0] * inv0));
        g_ctxp[w0 + 4] = __uint_as_float(f2t(oacc[et][1] * inv0));
        g_ctxp[w0 + 1] = __uint_as_float(f2t(oacc[et][2] * inv1));
        g_ctxp[w0 + 5] = __uint_as_float(f2t(oacc[et][3] * inv1));
    }
}

// ---------------------------------------------------------------------------
// Kernel 3: output projection. Packed A = g_ctxp, packed B = g_wop.
// grid = (8, 32). 3-stage ring, single sync per iter.
// ---------------------------------------------------------------------------
__global__ __launch_bounds__(256, 2) void proj_kernel(
    const float* __restrict__ bo, float* __restrict__ out)
{
    extern __shared__ uint32_t sm[];
    const uint32_t smA = smaddr(sm);
    const uint32_t smB = smA + 3 * TILE_W * 4;

    const int n0 = blockIdx.x * 128;
    const int m0 = blockIdx.y * 128;
    const int mg0 = m0 >> 4;
    const int ng0 = n0 >> 3;

    const int tid  = threadIdx.x;
    const int lane = tid & 31;
    const int warp = tid >> 5;
    const int g = lane >> 2, t = lane & 3;

    float acc[4][4][4];
    #pragma unroll
    for (int i = 0; i < 4; i++)
        #pragma unroll
        for (int j = 0; j < 4; j++)
            #pragma unroll
            for (int q = 0; q < 4; q++) acc[i][j][q] = 0.f;

    auto issue_tile = [&](int it2) {
        const int kd0 = it2 * 4;
        const int buf = it2 % 3;
        #pragma unroll
        for (int u = 0; u < 4; u++) {
            int w = (u * 256 + tid) * 4;
            int mgl = w >> 9, rem = w & 511;
            const float* src = g_ctxp + ((size_t)(mg0 + mgl) * 128 + kd0) * 128 + rem;
            CPA16(smA + (uint32_t)(buf * TILE_W + w) * 4, src);
        }
        #pragma unroll
        for (int u = 0; u < 4; u++) {
            int w = (u * 256 + tid) * 4;
            int ngl = w >> 8, rem = w & 255;
            const float* src = g_wop + ((size_t)(ng0 + ngl) * 128 + kd0) * 64 + rem;
            CPA16(smB + (uint32_t)(buf * TILE_W + w) * 4, src);
        }
        CPA_COMMIT();
    };

    issue_tile(0);
    issue_tile(1);

    for (int it = 0; it < 32; it++) {
        if (it == 31) { CPA_WAIT(0); } else { CPA_WAIT(1); }
        __syncthreads();
        if (it + 2 < 32) issue_tile(it + 2);

        const uint32_t* As_ = sm + (it % 3) * TILE_W;
        const uint32_t* Bs_ = sm + 3 * TILE_W + (it % 3) * TILE_W;
        #pragma unroll
        for (int ks = 0; ks < 4; ks++) {
            uint4 av[4];
            #pragma unroll
            for (int mt = 0; mt < 4; mt++)
                av[mt] = *(const uint4*)&As_[(((warp >> 2) * 4 + mt) * 4 + ks) * 128 + lane * 4];
            #pragma unroll
            for (int nt = 0; nt < 4; nt++) {
                uint2 bv2 = *(const uint2*)&Bs_[(((warp & 3) * 4 + nt) * 4 + ks) * 64 + lane * 2];
                #pragma unroll
                for (int mt = 0; mt < 4; mt++)
                    mma_tf32(acc[mt][nt], av[mt].x, av[mt].y, av[mt].z, av[mt].w,
                             bv2.x, bv2.y);
            }
        }
    }

    const int wm0 = (warp >> 2) * 64;
    const int wn0 = (warp & 3) * 32;
    #pragma unroll
    for (int mt = 0; mt < 4; mt++) {
        #pragma unroll
        for (int nt = 0; nt < 4; nt++) {
            int cb = n0 + wn0 + nt * 8 + 2 * t;
            float bi0 = bo[cb], bi1 = bo[cb + 1];
            #pragma unroll
            for (int half = 0; half < 2; half++) {
                int m = m0 + wm0 + mt * 16 + g + half * 8;
                float2 o = make_float2(acc[mt][nt][half * 2 + 0] + bi0,
                                       acc[mt][nt][half * 2 + 1] + bi1);
                *(float2*)&out[(size_t)m * DD + cb] = o;
            }
        }
    }
}

// ---------------------------------------------------------------------------
extern "C" void kernel_launch(void* const* d_in, const int* in_sizes, int n_in,
                              void* d_out, int out_size)
{
    (void)in_sizes; (void)n_in; (void)out_size;
    const float* x  = (const float*)d_in[0];
    const float* Wq = (const float*)d_in[1];
    const float* Wk = (const float*)d_in[2];
    const float* Wv = (const float*)d_in[3];
    const float* bq = (const float*)d_in[4];
    const float* bk = (const float*)d_in[5];
    const float* bv = (const float*)d_in[6];
    const float* Wo = (const float*)d_in[7];
    const float* bo = (const float*)d_in[8];
    float* out = (float*)d_out;

    cudaFuncSetAttribute(qkv_kernel,  cudaFuncAttributeMaxDynamicSharedMemorySize, GEMM_SMEM_BYTES);
    cudaFuncSetAttribute(proj_kernel, cudaFuncAttributeMaxDynamicSharedMemorySize, GEMM_SMEM_BYTES);
    cudaFuncSetAttribute(attn_kernel, cudaFuncAttributeMaxDynamicSharedMemorySize, ATTN_SMEM_BYTES);

    prep_pack<<<(unsigned)((PREP_TOTAL4 + 255) / 256), 256>>>(x, Wq, Wk, Wv, Wo);
    qkv_kernel<<<dim3(8, 32, 3), 256, GEMM_SMEM_BYTES>>>(bq, bk, bv);
    attn_kernel<<<dim3(16, 32), 256, ATTN_SMEM_BYTES>>>();
    proj_kernel<<<dim3(8, 32), 256, GEMM_SMEM_BYTES>>>(bo, out);
}

// round 9
// speedup vs baseline: 1.0469x; 1.0469x over previous
#include <cuda_runtime.h>
#include <cstdint>

// Problem constants
#define BB   2
#define SSL  2048
#define DD   1024
#define HH   16
#define DHH  64
#define MMR  (BB*SSL)   // 4096

// Scratch (__device__ globals; allocation-free rule). All values tf32-rounded.
// A-frag pack (16-row groups): word = ((mg*NKD+kd)*32 + (r&7)*4 + (d&3))*4
//                                     + ((r>>3)&1) + 2*((d>>2)&1)
// PAIRED B-frag pack (16-col groups = two 8-col frag groups interleaved):
//   word = ((ng2*NKD+kd)*32 + (n&7)*4 + (d&3))*4 + ((n>>3)&1)*2 + ((d>>2)&1)
// One LDS.128 yields (b0,b1) for BOTH 8-col subgroups.
__device__ float g_q[(size_t)BB*HH*SSL*DHH];   // per (b,h): A-frag pack, q*0.125*log2e
__device__ float g_k[(size_t)BB*HH*SSL*DHH];   // per (b,h): paired B-pack over (j, d)
__device__ float g_v[(size_t)BB*HH*SSL*DHH];   // per (b,h): per-64j-tile paired B-pack over (e, j)
__device__ float g_ctxp[(size_t)MMR*DD];       // ctx, A-frag pack
__device__ float g_xp[(size_t)MMR*DD];         // x,   A-frag pack
__device__ float g_wp[(size_t)3*HH*DD*DHH];    // W{q,k,v}, paired B-pack per head
__device__ float g_wop[(size_t)DD*DD];         // Wo, paired B-pack

// ---------------------------------------------------------------------------
// Helpers
// ---------------------------------------------------------------------------
__device__ __forceinline__ uint32_t f2t(float f) {
    uint32_t u;
    asm("cvt.rna.tf32.f32 %0, %1;" : "=r"(u) : "f"(f));
    return u;
}

__device__ __forceinline__ float ex2(float x) {
    float r;
    asm("ex2.approx.f32 %0, %1;" : "=f"(r) : "f"(x));
    return r;
}

__device__ __forceinline__ void mma_tf32(float* c,
                                         uint32_t a0, uint32_t a1, uint32_t a2, uint32_t a3,
                                         uint32_t b0, uint32_t b1) {
    asm volatile(
        "mma.sync.aligned.m16n8k8.row.col.f32.tf32.tf32.f32 "
        "{%0,%1,%2,%3}, {%4,%5,%6,%7}, {%8,%9}, {%0,%1,%2,%3};"
        : "+f"(c[0]), "+f"(c[1]), "+f"(c[2]), "+f"(c[3])
        : "r"(a0), "r"(a1), "r"(a2), "r"(a3), "r"(b0), "r"(b1));
}

__device__ __forceinline__ uint32_t smaddr(const void* p) {
    return (uint32_t)__cvta_generic_to_shared(p);
}
#define CPA16(dst, src) \
    asm volatile("cp.async.cg.shared.global [%0], [%1], 16;" :: "r"(dst), "l"(src))
#define CPA_COMMIT() asm volatile("cp.async.commit_group;")
#define CPA_WAIT(N)  asm volatile("cp.async.wait_group %0;" :: "n"(N))

// Q A-frag pack address (word index within one (b,h) plane)
__device__ __forceinline__ int qaddr(int r, int d) {
    return ((((r >> 4) * 8 + (d >> 3)) * 32 + (r & 7) * 4 + (d & 3)) << 2)
           | ((r >> 3) & 1) | (((d >> 2) & 1) << 1);
}

// ---------------------------------------------------------------------------
// Kernel 0: pack + tf32-round x / Wq / Wk / Wv / Wo into fragment layouts.
// ---------------------------------------------------------------------------
#define XN4  ((size_t)MMR*DD/4)          // 1048576
#define WN4  ((size_t)HH*DD*DHH/4)       // 262144
#define PREP_TOTAL4 (XN4 + 4*WN4)        // 2097152

__global__ __launch_bounds__(256) void prep_pack(
    const float* __restrict__ x,  const float* __restrict__ Wq,
    const float* __restrict__ Wk, const float* __restrict__ Wv,
    const float* __restrict__ Wo)
{
    size_t i = (size_t)blockIdx.x * 256 + threadIdx.x;
    if (i >= PREP_TOTAL4) return;
    if (i < XN4) {
        // x[r][d0..d0+3] -> g_xp (A-frag pack, NKD=128)
        int r = (int)(i >> 8), d0 = ((int)i & 255) * 4;
        float4 v = ((const float4*)x)[i];
        int mg = r >> 4, kd = d0 >> 3;
        int r8 = (r >> 3) & 1, d4 = (d0 >> 2) & 1;
        size_t w0 = ((((size_t)mg * 128 + kd) * 32 + (r & 7) * 4) << 2) + r8 + 2 * d4;
        g_xp[w0 +  0] = __uint_as_float(f2t(v.x));
        g_xp[w0 +  4] = __uint_as_float(f2t(v.y));
        g_xp[w0 +  8] = __uint_as_float(f2t(v.z));
        g_xp[w0 + 12] = __uint_as_float(f2t(v.w));
    } else if (i < XN4 + 3 * WN4) {
        // W[z][h][d][e0..e0+3] -> g_wp paired B-pack; per head: 4 ng2 x 16384 words
        size_t j = i - XN4;
        int z = (int)(j / WN4);
        int jr = (int)(j - (size_t)z * WN4);
        const float* W = (z == 0) ? Wq : (z == 1) ? Wk : Wv;
        float4 v = ((const float4*)W)[jr];
        int h = jr >> 14, d = (jr >> 4) & 1023, e0 = (jr & 15) * 4;
        int kd = d >> 3, t = d & 3, d4 = (d >> 2) & 1;
        int ng2 = e0 >> 4, sub = (e0 >> 3) & 1;
        size_t w0 = ((size_t)(z * 16 + h) * 4 + ng2) * 16384
                  + (((size_t)kd * 32 + (e0 & 7) * 4 + t) << 2) + sub * 2 + d4;
        g_wp[w0 +  0] = __uint_as_float(f2t(v.x));
        g_wp[w0 + 16] = __uint_as_float(f2t(v.y));
        g_wp[w0 + 32] = __uint_as_float(f2t(v.z));
        g_wp[w0 + 48] = __uint_as_float(f2t(v.w));
    } else {
        // Wo[d][n0..n0+3] -> g_wop paired B-pack; 64 ng2 x 16384 words
        size_t j = i - XN4 - 3 * WN4;
        float4 v = ((const float4*)Wo)[j];
        int d = (int)(j >> 8), n0 = ((int)j & 255) * 4;
        int kd = d >> 3, t = d & 3, d4 = (d >> 2) & 1;
        size_t w0 = (size_t)(n0 >> 4) * 16384
                  + (((size_t)kd * 32 + (n0 & 7) * 4 + t) << 2) + ((n0 >> 3) & 1) * 2 + d4;
        g_wop[w0 +  0] = __uint_as_float(f2t(v.x));
        g_wop[w0 + 16] = __uint_as_float(f2t(v.y));
        g_wop[w0 + 32] = __uint_as_float(f2t(v.z));
        g_wop[w0 + 48] = __uint_as_float(f2t(v.w));
    }
}

// ---------------------------------------------------------------------------
// GEMM core: block 128x128, BK=32, 8 warps (2m x 4n), warp 64x32.
// 3-stage cp.async ring, one __syncthreads per iter. Paired B-frags.
// ---------------------------------------------------------------------------
#define TILE_W 4096
#define GEMM_SMEM_BYTES (6 * TILE_W * 4)

// ---------------------------------------------------------------------------
// Kernel 1: fused QKV projection. grid=(8,32,3). Epilogue writes packed q/k/v.
// ---------------------------------------------------------------------------
__global__ __launch_bounds__(256, 2) void qkv_kernel(
    const float* __restrict__ bq, const float* __restrict__ bk, const float* __restrict__ bv)
{
    extern __shared__ uint32_t sm[];
    const uint32_t smA = smaddr(sm);                 // As: 3 * 4096 words
    const uint32_t smB = smA + 3 * TILE_W * 4;       // Bs: 3 * 4096 words

    const int z = blockIdx.z;
    const float* __restrict__ bias = (z == 0) ? bq : (z == 1) ? bk : bv;
    float* out = (z == 0) ? g_q : (z == 1) ? g_k : g_v;
    const float scale = (z == 0) ? 0.125f * 1.4426950408889634f : 1.0f;

    const int n0 = blockIdx.x * 128;
    const int m0 = blockIdx.y * 128;
    const int hA = n0 >> 6;
    const int mg0 = m0 >> 4;

    const int tid  = threadIdx.x;
    const int lane = tid & 31;
    const int warp = tid >> 5;
    const int g = lane >> 2, t = lane & 3;

    float acc[4][4][4];
    #pragma unroll
    for (int i = 0; i < 4; i++)
        #pragma unroll
        for (int j = 0; j < 4; j++)
            #pragma unroll
            for (int q = 0; q < 4; q++) acc[i][j][q] = 0.f;

    auto issue_tile = [&](int it2) {
        const int kd0 = it2 * 4;
        const int buf = it2 % 3;
        #pragma unroll
        for (int u = 0; u < 4; u++) {          // A tile
            int w = (u * 256 + tid) * 4;
            int mgl = w >> 9, rem = w & 511;
            const float* src = g_xp + ((size_t)(mg0 + mgl) * 128 + kd0) * 128 + rem;
            CPA16(smA + (uint32_t)(buf * TILE_W + w) * 4, src);
        }
        #pragma unroll
        for (int u = 0; u < 4; u++) {          // B tile (paired pack)
            int c = u * 256 + tid;
            int ng2l = c >> 7, kdl = (c >> 5) & 3, off = (c & 31) * 4;
            int h = hA + (ng2l >> 2);
            const float* src = g_wp + ((size_t)(z * 16 + h) * 4 + (ng2l & 3)) * 16384
                             + (size_t)(kd0 + kdl) * 128 + off;
            CPA16(smB + (uint32_t)(buf * TILE_W + c * 4) * 4, src);
        }
        CPA_COMMIT();
    };

    issue_tile(0);
    issue_tile(1);

    for (int it = 0; it < 32; it++) {
        if (it == 31) { CPA_WAIT(0); } else { CPA_WAIT(1); }
        __syncthreads();
        if (it + 2 < 32) issue_tile(it + 2);

        const uint32_t* As_ = sm + (it % 3) * TILE_W;
        const uint32_t* Bs_ = sm + 3 * TILE_W + (it % 3) * TILE_W;
        #pragma unroll
        for (int ks = 0; ks < 4; ks++) {
            uint4 av[4];
            #pragma unroll
            for (int mt = 0; mt < 4; mt++)
                av[mt] = *(const uint4*)&As_[(((warp >> 2) * 4 + mt) * 4 + ks) * 128 + lane * 4];
            #pragma unroll
            for (int nt2 = 0; nt2 < 2; nt2++) {
                uint4 b4 = *(const uint4*)&Bs_[((((warp & 3) * 2 + nt2) * 4 + ks) * 128) + lane * 4];
                #pragma unroll
                for (int mt = 0; mt < 4; mt++) {
                    mma_tf32(acc[mt][nt2 * 2 + 0], av[mt].x, av[mt].y, av[mt].z, av[mt].w,
                             b4.x, b4.y);
                    mma_tf32(acc[mt][nt2 * 2 + 1], av[mt].x, av[mt].y, av[mt].z, av[mt].w,
                             b4.z, b4.w);
                }
            }
        }
    }

    // Epilogue: bias + scale + tf32-round, scatter into packed q/k/v
    const int wm0 = (warp >> 2) * 64;
    const int wn0 = (warp & 3) * 32;
    #pragma unroll
    for (int mt = 0; mt < 4; mt++) {
        #pragma unroll
        for (int nt = 0; nt < 4; nt++) {
            int nb = (nt >> 1) * 16 + (nt & 1) * 8;
            int cb = n0 + wn0 + nb + 2 * t;
            float bi0 = bias[cb], bi1 = bias[cb + 1];
            int h = cb >> 6, e0 = cb & 63;
            #pragma unroll
            for (int half = 0; half < 2; half++) {
                int m = m0 + wm0 + mt * 16 + g + half * 8;
                int b = m >> 11, s = m & (SSL - 1);
                float* plane = out + (size_t)(b * HH + h) * (SSL * DHH);
                float v0 = (acc[mt][nt][half * 2 + 0] + bi0) * scale;
                float v1 = (acc[mt][nt][half * 2 + 1] + bi1) * scale;
                if (z == 0) {
                    plane[qaddr(s, e0)]     = __uint_as_float(f2t(v0));
                    plane[qaddr(s, e0 + 1)] = __uint_as_float(f2t(v1));
                } else if (z == 1) {
                    // K paired B-pack over (j=s, d=e)
                    size_t w = ((((size_t)(s >> 4) * 8 + (e0 >> 3)) * 32
                               + (s & 7) * 4 + (e0 & 3)) << 2)
                             + ((s >> 3) & 1) * 2 + ((e0 >> 2) & 1);
                    plane[w]     = __uint_as_float(f2t(v0));
                    plane[w + 4] = __uint_as_float(f2t(v1));
                } else {
                    // V per-64j-tile paired B-pack over (n=e, k=j=s)
                    size_t w = (size_t)(s >> 6) * 4096
                             + ((((size_t)(e0 >> 4) * 8 + ((s >> 3) & 7)) * 32
                               + (e0 & 7) * 4 + (s & 3)) << 2)
                             + ((e0 >> 3) & 1) * 2 + ((s >> 2) & 1);
                    plane[w]      = __uint_as_float(f2t(v0));
                    plane[w + 16] = __uint_as_float(f2t(v1));
                }
            }
        }
    }
}

// ---------------------------------------------------------------------------
// Kernel 2: flash attention. Paired K/V frags, P in per-warp A-frag smem,
// 2 barriers per kv-tile. q-tile 128, kv-tile 64, 32 tiles. 2 CTAs/SM.
// smem (words): Qs 8192 | Ks 4096 | Vs 4096 | Ps 8192 = 24576 -> 96KB
// ---------------------------------------------------------------------------
#define QS_OFF 0
#define KS_OFF 8192
#define VS_OFF 12288
#define PS_OFF 16384
#define ATTN_SMEM_BYTES (24576 * 4)

__global__ __launch_bounds__(256, 2) void attn_kernel()
{
    extern __shared__ uint32_t sm[];

    const int tid  = threadIdx.x;
    const int lane = tid & 31;
    const int warp = tid >> 5;
    const int g = lane >> 2, t = lane & 3;

    const int bh = blockIdx.y;
    const float* __restrict__ Qg = g_q + (size_t)bh * (SSL * DHH) + (size_t)blockIdx.x * 8192;
    const float* __restrict__ Kg = g_k + (size_t)bh * (SSL * DHH);
    const float* __restrict__ Vg = g_v + (size_t)bh * (SSL * DHH);

    const uint32_t smb = smaddr(sm);
    const int pbase = PS_OFF + warp * 1024;

    // Prologue: stage Q (group), then K(0) (group)
    #pragma unroll
    for (int u = 0; u < 8; u++) {
        int c = u * 256 + tid;
        CPA16(smb + (uint32_t)(QS_OFF + c * 4) * 4, Qg + c * 4);
    }
    CPA_COMMIT();
    #pragma unroll
    for (int u = 0; u < 4; u++) {
        int c = u * 256 + tid;
        CPA16(smb + (uint32_t)(KS_OFF + c * 4) * 4, Kg + c * 4);
    }
    CPA_COMMIT();

    float oacc[8][4];
    #pragma unroll
    for (int e = 0; e < 8; e++)
        #pragma unroll
        for (int q = 0; q < 4; q++) oacc[e][q] = 0.f;
    float mrun0 = -1e30f, mrun1 = -1e30f;
    float lrun0 = 0.f, lrun1 = 0.f;

    for (int i = 0; i < 32; i++) {
        CPA_WAIT(0);            // K(i) done (i=0: Q too)
        __syncthreads();        // B1: K visible; Vs free (all warps past PV(i-1))

        // Issue V(i) — lands during QK
        {
            const float* Vt = Vg + (size_t)i * 4096;
            #pragma unroll
            for (int u = 0; u < 4; u++) {
                int c = u * 256 + tid;
                CPA16(smb + (uint32_t)(VS_OFF + c * 4) * 4, Vt + c * 4);
            }
            CPA_COMMIT();
        }

        // S = Q K^T : paired K frags (one LDS.128 -> two col-blocks)
        float sf[8][4];
        #pragma unroll
        for (int jt = 0; jt < 8; jt++)
            #pragma unroll
            for (int q = 0; q < 4; q++) sf[jt][q] = 0.f;

        #pragma unroll
        for (int kd = 0; kd < 8; kd++) {
            uint4 aq = *(const uint4*)&sm[QS_OFF + ((warp * 8 + kd) * 32 + lane) * 4];
            #pragma unroll
            for (int jt2 = 0; jt2 < 4; jt2++) {
                uint4 kb = *(const uint4*)&sm[KS_OFF + ((jt2 * 8 + kd) * 32 + lane) * 4];
                mma_tf32(sf[jt2 * 2 + 0], aq.x, aq.y, aq.z, aq.w, kb.x, kb.y);
                mma_tf32(sf[jt2 * 2 + 1], aq.x, aq.y, aq.z, aq.w, kb.z, kb.w);
            }
        }

        CPA_WAIT(0);            // V(i) done
        __syncthreads();        // B2 (merged): V visible; Ks free

        // Issue K(i+1) — lands during softmax + PV + next B1
        if (i + 1 < 32) {
            const float* Kt = Kg + (size_t)(i + 1) * 4096;
            #pragma unroll
            for (int u = 0; u < 4; u++) {
                int c = u * 256 + tid;
                CPA16(smb + (uint32_t)(KS_OFF + c * 4) * 4, Kt + c * 4);
            }
            CPA_COMMIT();
        }

        // Online softmax in base-2 (scores carry log2e via q scale)
        float mx0 = -1e30f, mx1 = -1e30f;
        #pragma unroll
        for (int jt = 0; jt < 8; jt++) {
            mx0 = fmaxf(mx0, fmaxf(sf[jt][0], sf[jt][1]));
            mx1 = fmaxf(mx1, fmaxf(sf[jt][2], sf[jt][3]));
        }
        mx0 = fmaxf(mx0, __shfl_xor_sync(0xffffffffu, mx0, 1));
        mx0 = fmaxf(mx0, __shfl_xor_sync(0xffffffffu, mx0, 2));
        mx1 = fmaxf(mx1, __shfl_xor_sync(0xffffffffu, mx1, 1));
        mx1 = fmaxf(mx1, __shfl_xor_sync(0xffffffffu, mx1, 2));
        float mn0 = fmaxf(mrun0, mx0), mn1 = fmaxf(mrun1, mx1);
        float corr0 = ex2(mrun0 - mn0), corr1 = ex2(mrun1 - mn1);
        float sum0 = 0.f, sum1 = 0.f;
        #pragma unroll
        for (int jt = 0; jt < 8; jt++) {
            sf[jt][0] = ex2(sf[jt][0] - mn0);
            sf[jt][1] = ex2(sf[jt][1] - mn0);
            sf[jt][2] = ex2(sf[jt][2] - mn1);
            sf[jt][3] = ex2(sf[jt][3] - mn1);
            sum0 += sf[jt][0] + sf[jt][1];
            sum1 += sf[jt][2] + sf[jt][3];
        }
        sum0 += __shfl_xor_sync(0xffffffffu, sum0, 1);
        sum0 += __shfl_xor_sync(0xffffffffu, sum0, 2);
        sum1 += __shfl_xor_sync(0xffffffffu, sum1, 1);
        sum1 += __shfl_xor_sync(0xffffffffu, sum1, 2);
        lrun0 = lrun0 * corr0 + sum0; mrun0 = mn0;
        lrun1 = lrun1 * corr1 + sum1; mrun1 = mn1;
        #pragma unroll
        for (int e = 0; e < 8; e++) {
            oacc[e][0] *= corr0; oacc[e][1] *= corr0;
            oacc[e][2] *= corr1; oacc[e][3] *= corr1;
        }

        // Store P into per-warp A-frag pack (warp-private; syncwarp only)
        #pragma unroll
        for (int jt = 0; jt < 8; jt++) {
            uint32_t p0 = f2t(sf[jt][0]), p1 = f2t(sf[jt][1]);
            uint32_t p2 = f2t(sf[jt][2]), p3 = f2t(sf[jt][3]);
            int w0 = pbase + (jt * 32 + g * 4 + ((2 * t) & 3)) * 4 + ((t >> 1) & 1) * 2;
            *(uint2*)&sm[w0]     = make_uint2(p0, p2);   // (a0, a1) slots
            *(uint2*)&sm[w0 + 4] = make_uint2(p1, p3);
        }
        __syncwarp();

        // O += P V : paired V frags + vectorized P A-frags
        #pragma unroll
        for (int kj = 0; kj < 8; kj++) {
            uint4 pa = *(const uint4*)&sm[pbase + (kj * 32 + lane) * 4];
            #pragma unroll
            for (int et2 = 0; et2 < 4; et2++) {
                uint4 vb = *(const uint4*)&sm[VS_OFF + ((et2 * 8 + kj) * 32 + lane) * 4];
                mma_tf32(oacc[et2 * 2 + 0], pa.x, pa.y, pa.z, pa.w, vb.x, vb.y);
                mma_tf32(oacc[et2 * 2 + 1], pa.x, pa.y, pa.z, pa.w, vb.z, vb.w);
            }
        }
    }

    // Epilogue: normalize, tf32-round, write ctx in A-frag packed layout
    const int b = bh >> 4, h = bh & 15;
    const int m0 = blockIdx.x * 128;
    const float inv0 = 1.f / lrun0, inv1 = 1.f / lrun1;
    const int row0 = m0 + warp * 16 + g;
    const int mrow = (b << 11) + row0;
    const int mg = mrow >> 4;
    #pragma unroll
    for (int et = 0; et < 8; et++) {
        int d = h * DHH + et * 8 + 2 * t;
        int kd = d >> 3, d4 = (d >> 2) & 1;
        size_t w0 = ((((size_t)mg * 128 + kd) * 32 + (mrow & 7) * 4 + (d & 3)) << 2)
                  + 2 * d4;
        g_ctxp[w0 + 0] = __uint_as_float(f2t(oacc[et][0] * inv0));
        g_ctxp[w0 + 4] = __uint_as_float(f2t(oacc[et][1] * inv0));
        g_ctxp[w0 + 1] = __uint_as_float(f2t(oacc[et][2] * inv1));
        g_ctxp[w0 + 5] = __uint_as_float(f2t(oacc[et][3] * inv1));
    }
}

// ---------------------------------------------------------------------------
// Kernel 3: output projection. A = g_ctxp (A-pack), B = g_wop (paired pack).
// grid = (8, 32). 3-stage ring, single sync per iter.
// ---------------------------------------------------------------------------
__global__ __launch_bounds__(256, 2) void proj_kernel(
    const float* __restrict__ bo, float* __restrict__ out)
{
    extern __shared__ uint32_t sm[];
    const uint32_t smA = smaddr(sm);
    const uint32_t smB = smA + 3 * TILE_W * 4;

    const int n0 = blockIdx.x * 128;
    const int m0 = blockIdx.y * 128;
    const int mg0 = m0 >> 4;
    const int ng20 = n0 >> 4;

    const int tid  = threadIdx.x;
    const int lane = tid & 31;
    const int warp = tid >> 5;
    const int g = lane >> 2, t = lane & 3;

    float acc[4][4][4];
    #pragma unroll
    for (int i = 0; i < 4; i++)
        #pragma unroll
        for (int j = 0; j < 4; j++)
            #pragma unroll
            for (int q = 0; q < 4; q++) acc[i][j][q] = 0.f;

    auto issue_tile = [&](int it2) {
        const int kd0 = it2 * 4;
        const int buf = it2 % 3;
        #pragma unroll
        for (int u = 0; u < 4; u++) {
            int w = (u * 256 + tid) * 4;
            int mgl = w >> 9, rem = w & 511;
            const float* src = g_ctxp + ((size_t)(mg0 + mgl) * 128 + kd0) * 128 + rem;
            CPA16(smA + (uint32_t)(buf * TILE_W + w) * 4, src);
        }
        #pragma unroll
        for (int u = 0; u < 4; u++) {
            int c = u * 256 + tid;
            int ng2l = c >> 7, kdl = (c >> 5) & 3, off = (c & 31) * 4;
            const float* src = g_wop + (size_t)(ng20 + ng2l) * 16384
                             + (size_t)(kd0 + kdl) * 128 + off;
            CPA16(smB + (uint32_t)(buf * TILE_W + c * 4) * 4, src);
        }
        CPA_COMMIT();
    };

    issue_tile(0);
    issue_tile(1);

    for (int it = 0; it < 32; it++) {
        if (it == 31) { CPA_WAIT(0); } else { CPA_WAIT(1); }
        __syncthreads();
        if (it + 2 < 32) issue_tile(it + 2);

        const uint32_t* As_ = sm + (it % 3) * TILE_W;
        const uint32_t* Bs_ = sm + 3 * TILE_W + (it % 3) * TILE_W;
        #pragma unroll
        for (int ks = 0; ks < 4; ks++) {
            uint4 av[4];
            #pragma unroll
            for (int mt = 0; mt < 4; mt++)
                av[mt] = *(const uint4*)&As_[(((warp >> 2) * 4 + mt) * 4 + ks) * 128 + lane * 4];
            #pragma unroll
            for (int nt2 = 0; nt2 < 2; nt2++) {
                uint4 b4 = *(const uint4*)&Bs_[((((warp & 3) * 2 + nt2) * 4 + ks) * 128) + lane * 4];
                #pragma unroll
                for (int mt = 0; mt < 4; mt++) {
                    mma_tf32(acc[mt][nt2 * 2 + 0], av[mt].x, av[mt].y, av[mt].z, av[mt].w,
                             b4.x, b4.y);
                    mma_tf32(acc[mt][nt2 * 2 + 1], av[mt].x, av[mt].y, av[mt].z, av[mt].w,
                             b4.z, b4.w);
                }
            }
        }
    }

    const int wm0 = (warp >> 2) * 64;
    const int wn0 = (warp & 3) * 32;
    #pragma unroll
    for (int mt = 0; mt < 4; mt++) {
        #pragma unroll
        for (int nt = 0; nt < 4; nt++) {
            int nb = (nt >> 1) * 16 + (nt & 1) * 8;
            int cb = n0 + wn0 + nb + 2 * t;
            float bi0 = bo[cb], bi1 = bo[cb + 1];
            #pragma unroll
            for (int half = 0; half < 2; half++) {
                int m = m0 + wm0 + mt * 16 + g + half * 8;
                float2 o = make_float2(acc[mt][nt][half * 2 + 0] + bi0,
                                       acc[mt][nt][half * 2 + 1] + bi1);
                *(float2*)&out[(size_t)m * DD + cb] = o;
            }
        }
    }
}

// ---------------------------------------------------------------------------
extern "C" void kernel_launch(void* const* d_in, const int* in_sizes, int n_in,
                              void* d_out, int out_size)
{
    (void)in_sizes; (void)n_in; (void)out_size;
    const float* x  = (const float*)d_in[0];
    const float* Wq = (const float*)d_in[1];
    const float* Wk = (const float*)d_in[2];
    const float* Wv = (const float*)d_in[3];
    const float* bq = (const float*)d_in[4];
    const float* bk = (const float*)d_in[5];
    const float* bv = (const float*)d_in[6];
    const float* Wo = (const float*)d_in[7];
    const float* bo = (const float*)d_in[8];
    float* out = (float*)d_out;

    cudaFuncSetAttribute(qkv_kernel,  cudaFuncAttributeMaxDynamicSharedMemorySize, GEMM_SMEM_BYTES);
    cudaFuncSetAttribute(proj_kernel, cudaFuncAttributeMaxDynamicSharedMemorySize, GEMM_SMEM_BYTES);
    cudaFuncSetAttribute(attn_kernel, cudaFuncAttributeMaxDynamicSharedMemorySize, ATTN_SMEM_BYTES);

    prep_pack<<<(unsigned)((PREP_TOTAL4 + 255) / 256), 256>>>(x, Wq, Wk, Wv, Wo);
    qkv_kernel<<<dim3(8, 32, 3), 256, GEMM_SMEM_BYTES>>>(bq, bk, bv);
    attn_kernel<<<dim3(16, 32), 256, ATTN_SMEM_BYTES>>>();
    proj_kernel<<<dim3(8, 32), 256, GEMM_SMEM_BYTES>>>(bo, out);
}